// round 2
// baseline (speedup 1.0000x reference)
#include <cuda_runtime.h>
#include <cstdint>

#define SD 32
#define OC 16
#define NMAX 50000
#define EMAX 800000
#define BN_EPS 1e-5f

__device__ float g_T2[(size_t)NMAX * 512];
__device__ float g_h [(size_t)EMAX * 32];
__device__ float g_B [NMAX * OC];
__device__ float g_agg[NMAX * OC];
__device__ float g_n1[NMAX * 32];
__device__ float g_n2[NMAX * 32];
__device__ float g_w3r[32 * 512];
__device__ int   g_src[EMAX];
__device__ int   g_dst[EMAX];
__device__ float g_sums[4 * 64];
__device__ float g_bnp [4 * 64];
__device__ int   g_is64;

__device__ __forceinline__ void red_add_v4(float* addr, float4 v) {
    asm volatile("red.global.add.v4.f32 [%0], {%1, %2, %3, %4};"
                 :: "l"(addr), "f"(v.x), "f"(v.y), "f"(v.z), "f"(v.w) : "memory");
}

__global__ void k_zero() { g_sums[threadIdx.x] = 0.0f; }

__global__ void k_detect(const void* idx, long ewords, int nmax) {
    __shared__ int bad;
    if (threadIdx.x == 0) bad = 0;
    __syncthreads();
    long i = ((long)threadIdx.x * 12347L) % ewords;
    long long v = ((const long long*)idx)[i];
    if (v < 0 || v >= (long long)nmax) atomicOr(&bad, 1);
    __syncthreads();
    if (threadIdx.x == 0) g_is64 = bad ? 0 : 1;
}

__global__ void k_convert(const void* idx, long E) {
    long e = blockIdx.x * 256L + threadIdx.x;
    if (e >= E) return;
    if (g_is64) {
        const long long* p = (const long long*)idx;
        g_src[e] = (int)p[e];
        g_dst[e] = (int)p[E + e];
    } else {
        const int* p = (const int*)idx;
        g_src[e] = p[e];
        g_dst[e] = p[E + e];
    }
}

__global__ void k_w3r(const float* __restrict__ w3) {
    int t = blockIdx.x * 256 + threadIdx.x;
    int i = t >> 9, oh = t & 511, o = oh >> 5, h = oh & 31;
    g_w3r[t] = w3[h * 512 + i * 16 + o];
}

// T2: [N,32] @ [32,512], 32 nodes per block, w3r cached in smem
__global__ void k_T(const float* __restrict__ x, int N) {
    extern __shared__ float sm[];
    float* ws = sm;            // 16384
    float* xs = sm + 16384;    // 1024
    int tid = threadIdx.x;
    for (int t = tid; t < 16384; t += 256) ws[t] = g_w3r[t];
    int vb = blockIdx.x * 32;
    for (int t = tid; t < 1024; t += 256) {
        int v = vb + (t >> 5);
        xs[t] = (v < N) ? x[(size_t)v * 32 + (t & 31)] : 0.0f;
    }
    __syncthreads();
    int w = tid >> 5, lane = tid & 31;
    float4 acc[4][4];
#pragma unroll
    for (int r = 0; r < 4; r++)
#pragma unroll
        for (int k = 0; k < 4; k++) acc[r][k] = make_float4(0, 0, 0, 0);
#pragma unroll 8
    for (int i = 0; i < 32; i++) {
        float a0 = xs[(w * 4 + 0) * 32 + i];
        float a1 = xs[(w * 4 + 1) * 32 + i];
        float a2 = xs[(w * 4 + 2) * 32 + i];
        float a3 = xs[(w * 4 + 3) * 32 + i];
#pragma unroll
        for (int k = 0; k < 4; k++) {
            float4 wv = *(const float4*)&ws[i * 512 + lane * 4 + k * 128];
            acc[0][k].x += a0 * wv.x; acc[0][k].y += a0 * wv.y; acc[0][k].z += a0 * wv.z; acc[0][k].w += a0 * wv.w;
            acc[1][k].x += a1 * wv.x; acc[1][k].y += a1 * wv.y; acc[1][k].z += a1 * wv.z; acc[1][k].w += a1 * wv.w;
            acc[2][k].x += a2 * wv.x; acc[2][k].y += a2 * wv.y; acc[2][k].z += a2 * wv.z; acc[2][k].w += a2 * wv.w;
            acc[3][k].x += a3 * wv.x; acc[3][k].y += a3 * wv.y; acc[3][k].z += a3 * wv.z; acc[3][k].w += a3 * wv.w;
        }
    }
#pragma unroll
    for (int r = 0; r < 4; r++) {
        int v = vb + w * 4 + r;
        if (v < N) {
#pragma unroll
            for (int k = 0; k < 4; k++)
                *(float4*)&g_T2[(size_t)v * 512 + lane * 4 + k * 128] = acc[r][k];
        }
    }
}

__global__ void k_rootB(const float* __restrict__ x, const float* __restrict__ rw,
                        const float* __restrict__ rb, const float* __restrict__ b3, int N) {
    __shared__ float rws[512], b3s[512], rbs[16];
    int tid = threadIdx.x;
    for (int t = tid; t < 512; t += 256) { rws[t] = rw[t]; b3s[t] = b3[t]; }
    if (tid < 16) rbs[tid] = rb[tid];
    __syncthreads();
    int v = blockIdx.x * 256 + tid;
    if (v >= N) return;
    float a[32];
    const float4* xr = (const float4*)(x + (size_t)v * 32);
#pragma unroll
    for (int k = 0; k < 8; k++) {
        float4 t4 = xr[k];
        a[4*k] = t4.x; a[4*k+1] = t4.y; a[4*k+2] = t4.z; a[4*k+3] = t4.w;
    }
    float accr[16], accb[16];
#pragma unroll
    for (int o = 0; o < 16; o++) { accr[o] = rbs[o]; accb[o] = 0.0f; }
#pragma unroll 8
    for (int i = 0; i < 32; i++) {
        float av = a[i];
#pragma unroll
        for (int o = 0; o < 16; o++) {
            accr[o] += av * rws[i * 16 + o];
            accb[o] += av * b3s[i * 16 + o];
        }
    }
#pragma unroll
    for (int o = 0; o < 16; o++) {
        g_agg[(size_t)v * 16 + o] = accr[o];
        g_B[(size_t)v * 16 + o]   = accb[o];
    }
}

// generic 32->32 row GEMM body used by several kernels via macro
#define GEMM32_BODY(INPUT_EXPR, OUT_PTR) \
    float acc[32]; \
    _Pragma("unroll") for (int j = 0; j < 32; j++) acc[j] = bsm[j]; \
    _Pragma("unroll 8") for (int i = 0; i < 32; i++) { \
        float av = a[i]; \
        _Pragma("unroll") for (int j4 = 0; j4 < 8; j4++) { \
            float4 wv = *(const float4*)&wsm[i * 32 + j4 * 4]; \
            acc[j4*4+0] += av * wv.x; acc[j4*4+1] += av * wv.y; \
            acc[j4*4+2] += av * wv.z; acc[j4*4+3] += av * wv.w; } } \
    float4* outr = (float4*)(OUT_PTR); \
    _Pragma("unroll") for (int k = 0; k < 8; k++) \
        outr[k] = make_float4(acc[4*k], acc[4*k+1], acc[4*k+2], acc[4*k+3]);

__global__ void k_edge1(const float* __restrict__ A, const float* __restrict__ w,
                        const float* __restrict__ b, long E) {
    __shared__ float wsm[1024], bsm[32];
    int tid = threadIdx.x;
    for (int t = tid; t < 1024; t += 256) wsm[t] = w[t];
    if (tid < 32) bsm[tid] = b[tid];
    __syncthreads();
    long e = blockIdx.x * 256L + tid;
    if (e >= E) return;
    float a[32];
    const float4* ar = (const float4*)(A + e * 32);
#pragma unroll
    for (int k = 0; k < 8; k++) {
        float4 t4 = ar[k];
        a[4*k] = t4.x; a[4*k+1] = t4.y; a[4*k+2] = t4.z; a[4*k+3] = t4.w;
    }
    GEMM32_BODY(, g_h + e * 32)
}

__global__ void k_edge2(const float* __restrict__ w, const float* __restrict__ b, long E) {
    __shared__ float wsm[1024], bsm[32], sc[32], sh[32];
    int tid = threadIdx.x;
    for (int t = tid; t < 1024; t += 256) wsm[t] = w[t];
    if (tid < 32) { bsm[tid] = b[tid]; sc[tid] = g_bnp[tid]; sh[tid] = g_bnp[32 + tid]; }
    __syncthreads();
    long e = blockIdx.x * 256L + tid;
    if (e >= E) return;
    float a[32];
    const float4* ar = (const float4*)(g_h + e * 32);
#pragma unroll
    for (int k = 0; k < 8; k++) {
        float4 t4 = ar[k];
        a[4*k+0] = fmaxf(t4.x * sc[4*k+0] + sh[4*k+0], 0.0f);
        a[4*k+1] = fmaxf(t4.y * sc[4*k+1] + sh[4*k+1], 0.0f);
        a[4*k+2] = fmaxf(t4.z * sc[4*k+2] + sh[4*k+2], 0.0f);
        a[4*k+3] = fmaxf(t4.w * sc[4*k+3] + sh[4*k+3], 0.0f);
    }
    GEMM32_BODY(, g_h + e * 32)
}

__global__ void k_stat(int which, long n4, int stage) {
    const float4* d = (which == 0) ? (const float4*)g_h
                    : (which == 1) ? (const float4*)g_n1
                                   : (const float4*)g_n2;
    float* out = &g_sums[stage * 64];
    long tid = blockIdx.x * 256L + threadIdx.x;
    long stride = (long)gridDim.x * 256L;
    float4 s = make_float4(0,0,0,0), q = make_float4(0,0,0,0);
    for (long i = tid; i < n4; i += stride) {
        float4 v = d[i];
        s.x += v.x; s.y += v.y; s.z += v.z; s.w += v.w;
        q.x += v.x*v.x; q.y += v.y*v.y; q.z += v.z*v.z; q.w += v.w*v.w;
    }
#pragma unroll
    for (int off = 8; off < 32; off <<= 1) {
        s.x += __shfl_xor_sync(0xffffffffu, s.x, off);
        s.y += __shfl_xor_sync(0xffffffffu, s.y, off);
        s.z += __shfl_xor_sync(0xffffffffu, s.z, off);
        s.w += __shfl_xor_sync(0xffffffffu, s.w, off);
        q.x += __shfl_xor_sync(0xffffffffu, q.x, off);
        q.y += __shfl_xor_sync(0xffffffffu, q.y, off);
        q.z += __shfl_xor_sync(0xffffffffu, q.z, off);
        q.w += __shfl_xor_sync(0xffffffffu, q.w, off);
    }
    int lane = threadIdx.x & 31;
    if (lane < 8) {
        int cb = lane * 4;
        atomicAdd(&out[cb+0], s.x); atomicAdd(&out[cb+1], s.y);
        atomicAdd(&out[cb+2], s.z); atomicAdd(&out[cb+3], s.w);
        atomicAdd(&out[32+cb+0], q.x); atomicAdd(&out[32+cb+1], q.y);
        atomicAdd(&out[32+cb+2], q.z); atomicAdd(&out[32+cb+3], q.w);
    }
}

__global__ void k_fin(int stage, const float* __restrict__ g, const float* __restrict__ be, float n) {
    int j = threadIdx.x;
    float s = g_sums[stage * 64 + j];
    float sq = g_sums[stage * 64 + 32 + j];
    float m = s / n;
    float var = sq / n - m * m;
    float scale = g[j] * rsqrtf(var + BN_EPS);
    g_bnp[stage * 64 + j] = scale;
    g_bnp[stage * 64 + 32 + j] = be[j] - m * scale;
}

// edge einsum + scatter: one warp per edge. lane = o*2+p; h range = [p*16, p*16+16)
__global__ void k_edge3(long E) {
    __shared__ float sc[32], sh[32];
    __shared__ float smsg[8][16];
    int tid = threadIdx.x;
    if (tid < 32) { sc[tid] = g_bnp[64 + tid]; sh[tid] = g_bnp[96 + tid]; }
    __syncthreads();
    long e = (blockIdx.x * 256L + tid) >> 5;
    if (e >= E) return;
    int lane = tid & 31, wid = tid >> 5;
    int o = lane >> 1, p = lane & 1;
    int s = g_src[e];
    int d = g_dst[e];
    const float4* hrow = (const float4*)(g_h + e * 32 + p * 16);
    const float4* trow = (const float4*)(g_T2 + (size_t)s * 512 + lane * 16);
    float acc = 0.0f;
#pragma unroll
    for (int k = 0; k < 4; k++) {
        float4 z = hrow[k];
        float4 t = trow[k];
        int hb = p * 16 + k * 4;
        z.x = fmaxf(z.x * sc[hb+0] + sh[hb+0], 0.0f);
        z.y = fmaxf(z.y * sc[hb+1] + sh[hb+1], 0.0f);
        z.z = fmaxf(z.z * sc[hb+2] + sh[hb+2], 0.0f);
        z.w = fmaxf(z.w * sc[hb+3] + sh[hb+3], 0.0f);
        acc += z.x*t.x + z.y*t.y + z.z*t.z + z.w*t.w;
    }
    acc += __shfl_xor_sync(0xffffffffu, acc, 1);
    if (p == 0) smsg[wid][o] = acc + g_B[(size_t)s * 16 + o];
    __syncwarp();
    if (lane < 4) {
        float4 m = *(float4*)&smsg[wid][lane * 4];
        red_add_v4(&g_agg[(size_t)d * 16 + lane * 4], m);
    }
}

__global__ void k_own1(const float* __restrict__ x, const float* __restrict__ w,
                       const float* __restrict__ b, int N) {
    __shared__ float wsm[1536], bsm[32];
    int tid = threadIdx.x;
    for (int t = tid; t < 1536; t += 256) wsm[t] = w[t];
    if (tid < 32) bsm[tid] = b[tid];
    __syncthreads();
    int v = blockIdx.x * 256 + tid;
    if (v >= N) return;
    float a[48];
    const float4* xr = (const float4*)(x + (size_t)v * 32);
#pragma unroll
    for (int k = 0; k < 8; k++) {
        float4 t4 = xr[k];
        a[4*k] = t4.x; a[4*k+1] = t4.y; a[4*k+2] = t4.z; a[4*k+3] = t4.w;
    }
    const float4* gr = (const float4*)(g_agg + (size_t)v * 16);
#pragma unroll
    for (int k = 0; k < 4; k++) {
        float4 t4 = gr[k];
        a[32+4*k] = t4.x; a[32+4*k+1] = t4.y; a[32+4*k+2] = t4.z; a[32+4*k+3] = t4.w;
    }
    float acc[32];
#pragma unroll
    for (int j = 0; j < 32; j++) acc[j] = bsm[j];
#pragma unroll 8
    for (int i = 0; i < 48; i++) {
        float av = a[i];
#pragma unroll
        for (int j4 = 0; j4 < 8; j4++) {
            float4 wv = *(const float4*)&wsm[i * 32 + j4 * 4];
            acc[j4*4+0] += av * wv.x; acc[j4*4+1] += av * wv.y;
            acc[j4*4+2] += av * wv.z; acc[j4*4+3] += av * wv.w;
        }
    }
    float4* outr = (float4*)(g_n1 + (size_t)v * 32);
#pragma unroll
    for (int k = 0; k < 8; k++)
        outr[k] = make_float4(acc[4*k], acc[4*k+1], acc[4*k+2], acc[4*k+3]);
}

__global__ void k_own2(const float* __restrict__ w, const float* __restrict__ b, int N) {
    __shared__ float wsm[1024], bsm[32], sc[32], sh[32];
    int tid = threadIdx.x;
    for (int t = tid; t < 1024; t += 256) wsm[t] = w[t];
    if (tid < 32) { bsm[tid] = b[tid]; sc[tid] = g_bnp[128 + tid]; sh[tid] = g_bnp[160 + tid]; }
    __syncthreads();
    int v = blockIdx.x * 256 + tid;
    if (v >= N) return;
    float a[32];
    const float4* ar = (const float4*)(g_n1 + (size_t)v * 32);
#pragma unroll
    for (int k = 0; k < 8; k++) {
        float4 t4 = ar[k];
        a[4*k+0] = fmaxf(t4.x * sc[4*k+0] + sh[4*k+0], 0.0f);
        a[4*k+1] = fmaxf(t4.y * sc[4*k+1] + sh[4*k+1], 0.0f);
        a[4*k+2] = fmaxf(t4.z * sc[4*k+2] + sh[4*k+2], 0.0f);
        a[4*k+3] = fmaxf(t4.w * sc[4*k+3] + sh[4*k+3], 0.0f);
    }
    GEMM32_BODY(, g_n2 + (size_t)v * 32)
}

__global__ void k_own3(const float* __restrict__ w, const float* __restrict__ b,
                       float* __restrict__ out, int N) {
    __shared__ float wsm[1024], bsm[32], sc[32], sh[32];
    int tid = threadIdx.x;
    for (int t = tid; t < 1024; t += 256) wsm[t] = w[t];
    if (tid < 32) { bsm[tid] = b[tid]; sc[tid] = g_bnp[192 + tid]; sh[tid] = g_bnp[224 + tid]; }
    __syncthreads();
    int v = blockIdx.x * 256 + tid;
    if (v >= N) return;
    float a[32];
    const float4* ar = (const float4*)(g_n2 + (size_t)v * 32);
#pragma unroll
    for (int k = 0; k < 8; k++) {
        float4 t4 = ar[k];
        a[4*k+0] = fmaxf(t4.x * sc[4*k+0] + sh[4*k+0], 0.0f);
        a[4*k+1] = fmaxf(t4.y * sc[4*k+1] + sh[4*k+1], 0.0f);
        a[4*k+2] = fmaxf(t4.z * sc[4*k+2] + sh[4*k+2], 0.0f);
        a[4*k+3] = fmaxf(t4.w * sc[4*k+3] + sh[4*k+3], 0.0f);
    }
    GEMM32_BODY(, out + (size_t)v * 32)
}

extern "C" void kernel_launch(void* const* d_in, const int* in_sizes, int n_in,
                              void* d_out, int out_size) {
    const float* x    = (const float*)d_in[0];
    const float* ea   = (const float*)d_in[1];
    const void*  ei   = d_in[2];
    const float* mw1  = (const float*)d_in[3];
    const float* mb1  = (const float*)d_in[4];
    const float* mg1  = (const float*)d_in[5];
    const float* mbe1 = (const float*)d_in[6];
    const float* mw2  = (const float*)d_in[7];
    const float* mb2  = (const float*)d_in[8];
    const float* mg2  = (const float*)d_in[9];
    const float* mbe2 = (const float*)d_in[10];
    const float* mw3  = (const float*)d_in[11];
    const float* mb3  = (const float*)d_in[12];
    const float* rw   = (const float*)d_in[13];
    const float* rb   = (const float*)d_in[14];
    const float* ow1  = (const float*)d_in[15];
    const float* ob1  = (const float*)d_in[16];
    const float* og1  = (const float*)d_in[17];
    const float* obe1 = (const float*)d_in[18];
    const float* ow2  = (const float*)d_in[19];
    const float* ob2  = (const float*)d_in[20];
    const float* og2  = (const float*)d_in[21];
    const float* obe2 = (const float*)d_in[22];
    const float* ow3  = (const float*)d_in[23];
    const float* ob3  = (const float*)d_in[24];
    float* out = (float*)d_out;

    int  N = in_sizes[0] / SD;
    long E = (long)in_sizes[1] / SD;

    cudaFuncSetAttribute(k_T, cudaFuncAttributeMaxDynamicSharedMemorySize, 69632);

    int nb256  = (N + 255) / 256;
    long eb256 = (E + 255) / 256;
    long eb3   = (E * 32 + 255) / 256;

    k_zero<<<1, 256>>>();
    k_detect<<<1, 256>>>(ei, E, N);
    k_convert<<<(unsigned)eb256, 256>>>(ei, E);
    k_w3r<<<64, 256>>>(mw3);
    k_T<<<(N + 31) / 32, 256, 69632>>>(x, N);
    k_rootB<<<nb256, 256>>>(x, rw, rb, mb3, N);
    k_edge1<<<(unsigned)eb256, 256>>>(ea, mw1, mb1, E);
    k_stat<<<1024, 256>>>(0, E * 8, 0);
    k_fin<<<1, 32>>>(0, mg1, mbe1, (float)E);
    k_edge2<<<(unsigned)eb256, 256>>>(mw2, mb2, E);
    k_stat<<<1024, 256>>>(0, E * 8, 1);
    k_fin<<<1, 32>>>(1, mg2, mbe2, (float)E);
    k_edge3<<<(unsigned)eb3, 256>>>(E);
    k_own1<<<nb256, 256>>>(x, ow1, ob1, N);
    k_stat<<<512, 256>>>(1, (long)N * 8, 2);
    k_fin<<<1, 32>>>(2, og1, obe1, (float)N);
    k_own2<<<nb256, 256>>>(ow2, ob2, N);
    k_stat<<<512, 256>>>(2, (long)N * 8, 3);
    k_fin<<<1, 32>>>(3, og2, obe2, (float)N);
    k_own3<<<nb256, 256>>>(ow3, ob3, out, N);
}

// round 3
// speedup vs baseline: 1.9029x; 1.9029x over previous
#include <cuda_runtime.h>
#include <cuda_fp16.h>
#include <cstdint>

#define SD 32
#define OC 16
#define NMAX 50000
#define EMAX 800000
#define BN_EPS 1e-5f

__device__ __half g_T2h[(size_t)NMAX * 512];
__device__ float g_h [(size_t)EMAX * 32];
__device__ float g_B [NMAX * OC];
__device__ float g_agg[NMAX * OC];
__device__ float g_n1[NMAX * 32];
__device__ float g_n2[NMAX * 32];
__device__ float g_w3r[32 * 512];
__device__ int   g_src[EMAX];
__device__ int   g_dst[EMAX];
__device__ float g_sums[4 * 64];
__device__ float g_bnp [4 * 64];
__device__ int   g_is64;

typedef unsigned long long u64;

__device__ __forceinline__ u64 pk2(float lo, float hi) {
    u64 r; asm("mov.b64 %0, {%1, %2};" : "=l"(r) : "f"(lo), "f"(hi)); return r;
}
__device__ __forceinline__ float2 upk2(u64 v) {
    float2 f; asm("mov.b64 {%0, %1}, %2;" : "=f"(f.x), "=f"(f.y) : "l"(v)); return f;
}
__device__ __forceinline__ void fma2(u64& d, u64 a, u64 b) {
    asm("fma.rn.f32x2 %0, %1, %2, %0;" : "+l"(d) : "l"(a), "l"(b));
}
__device__ __forceinline__ void red_add_v4(float* addr, float4 v) {
    asm volatile("red.global.add.v4.f32 [%0], {%1, %2, %3, %4};"
                 :: "l"(addr), "f"(v.x), "f"(v.y), "f"(v.z), "f"(v.w) : "memory");
}

__global__ void k_detect(const void* idx, long ewords, int nmax) {
    __shared__ int bad;
    if (threadIdx.x == 0) bad = 0;
    __syncthreads();
    long i = ((long)threadIdx.x * 12347L) % ewords;
    long long v = ((const long long*)idx)[i];
    if (v < 0 || v >= (long long)nmax) atomicOr(&bad, 1);
    __syncthreads();
    if (threadIdx.x == 0) g_is64 = bad ? 0 : 1;
}

__global__ void k_convert(const void* idx, long E) {
    long e = blockIdx.x * 256L + threadIdx.x;
    if (e >= E) return;
    if (g_is64) {
        const long long* p = (const long long*)idx;
        g_src[e] = (int)p[e];
        g_dst[e] = (int)p[E + e];
    } else {
        const int* p = (const int*)idx;
        g_src[e] = p[e];
        g_dst[e] = p[E + e];
    }
}

// w3 rearrange + zero stat accumulators (fused)
__global__ void k_w3rz(const float* __restrict__ w3) {
    int t = blockIdx.x * 256 + threadIdx.x;
    int i = t >> 9, oh = t & 511, o = oh >> 5, h = oh & 31;
    g_w3r[t] = w3[h * 512 + i * 16 + o];
    if (blockIdx.x == 0) g_sums[threadIdx.x] = 0.0f;
}

// T2h: [N,32] @ [32,512] -> fp16 store. 32 nodes/block, w3r in smem.
__global__ void k_T(const float* __restrict__ x, int N) {
    extern __shared__ float sm[];
    float* ws = sm;            // 16384
    float* xs = sm + 16384;    // 1024
    int tid = threadIdx.x;
    for (int t = tid; t < 16384; t += 256) ws[t] = g_w3r[t];
    int vb = blockIdx.x * 32;
    for (int t = tid; t < 1024; t += 256) {
        int v = vb + (t >> 5);
        xs[t] = (v < N) ? x[(size_t)v * 32 + (t & 31)] : 0.0f;
    }
    __syncthreads();
    int w = tid >> 5, lane = tid & 31;
    u64 acc[4][8];
#pragma unroll
    for (int r = 0; r < 4; r++)
#pragma unroll
        for (int k = 0; k < 8; k++) acc[r][k] = 0ULL;
#pragma unroll 8
    for (int i = 0; i < 32; i++) {
        u64 a0 = pk2(xs[(w*4+0)*32 + i], xs[(w*4+0)*32 + i]);
        u64 a1 = pk2(xs[(w*4+1)*32 + i], xs[(w*4+1)*32 + i]);
        u64 a2 = pk2(xs[(w*4+2)*32 + i], xs[(w*4+2)*32 + i]);
        u64 a3 = pk2(xs[(w*4+3)*32 + i], xs[(w*4+3)*32 + i]);
#pragma unroll
        for (int k = 0; k < 4; k++) {
            ulonglong2 w2 = *(const ulonglong2*)&ws[i * 512 + lane * 4 + k * 128];
            fma2(acc[0][2*k], a0, w2.x); fma2(acc[0][2*k+1], a0, w2.y);
            fma2(acc[1][2*k], a1, w2.x); fma2(acc[1][2*k+1], a1, w2.y);
            fma2(acc[2][2*k], a2, w2.x); fma2(acc[2][2*k+1], a2, w2.y);
            fma2(acc[3][2*k], a3, w2.x); fma2(acc[3][2*k+1], a3, w2.y);
        }
    }
#pragma unroll
    for (int r = 0; r < 4; r++) {
        int v = vb + w * 4 + r;
        if (v < N) {
#pragma unroll
            for (int k = 0; k < 4; k++) {
                float2 u0 = upk2(acc[r][2*k]), u1 = upk2(acc[r][2*k+1]);
                __half2 h0 = __floats2half2_rn(u0.x, u0.y);
                __half2 h1 = __floats2half2_rn(u1.x, u1.y);
                uint2 st;
                st.x = *(unsigned*)&h0; st.y = *(unsigned*)&h1;
                *(uint2*)((char*)g_T2h + ((size_t)v * 512 + lane * 4 + k * 128) * 2) = st;
            }
        }
    }
}

__global__ void k_rootB(const float* __restrict__ x, const float* __restrict__ rw,
                        const float* __restrict__ rb, const float* __restrict__ b3, int N) {
    __shared__ float rws[512], b3s[512], rbs[16];
    int tid = threadIdx.x;
    for (int t = tid; t < 512; t += 256) { rws[t] = rw[t]; b3s[t] = b3[t]; }
    if (tid < 16) rbs[tid] = rb[tid];
    __syncthreads();
    int v = blockIdx.x * 256 + tid;
    if (v >= N) return;
    float a[32];
    const float4* xr = (const float4*)(x + (size_t)v * 32);
#pragma unroll
    for (int k = 0; k < 8; k++) {
        float4 t4 = xr[k];
        a[4*k] = t4.x; a[4*k+1] = t4.y; a[4*k+2] = t4.z; a[4*k+3] = t4.w;
    }
    float accr[16], accb[16];
#pragma unroll
    for (int o = 0; o < 16; o++) { accr[o] = rbs[o]; accb[o] = 0.0f; }
#pragma unroll 8
    for (int i = 0; i < 32; i++) {
        float av = a[i];
#pragma unroll
        for (int o = 0; o < 16; o++) {
            accr[o] += av * rws[i * 16 + o];
            accb[o] += av * b3s[i * 16 + o];
        }
    }
#pragma unroll
    for (int o = 0; o < 16; o++) {
        g_agg[(size_t)v * 16 + o] = accr[o];
        g_B[(size_t)v * 16 + o]   = accb[o];
    }
}

// packed-f32x2 32->32 GEMM body (wsm weights, bsm bias, a[] input regs)
#define GEMM32_BODY(NI, OUT_PTR) \
    u64 acc2[16]; \
    _Pragma("unroll") for (int j = 0; j < 16; j++) acc2[j] = pk2(bsm[2*j], bsm[2*j+1]); \
    _Pragma("unroll 8") for (int i = 0; i < NI; i++) { \
        u64 av = pk2(a[i], a[i]); \
        const ulonglong2* wrow = (const ulonglong2*)&wsm[i * 32]; \
        _Pragma("unroll") for (int j = 0; j < 8; j++) { \
            ulonglong2 w2 = wrow[j]; \
            fma2(acc2[2*j], av, w2.x); fma2(acc2[2*j+1], av, w2.y); } } \
    float4* outr = (float4*)(OUT_PTR); \
    _Pragma("unroll") for (int k = 0; k < 8; k++) { \
        float2 u0 = upk2(acc2[2*k]), u1 = upk2(acc2[2*k+1]); \
        outr[k] = make_float4(u0.x, u0.y, u1.x, u1.y); }

__global__ void k_edge1(const float* __restrict__ A, const float* __restrict__ w,
                        const float* __restrict__ b, long E) {
    __shared__ float wsm[1024], bsm[32];
    int tid = threadIdx.x;
    for (int t = tid; t < 1024; t += 256) wsm[t] = w[t];
    if (tid < 32) bsm[tid] = b[tid];
    __syncthreads();
    long e = blockIdx.x * 256L + tid;
    if (e >= E) return;
    float a[32];
    const float4* ar = (const float4*)(A + e * 32);
#pragma unroll
    for (int k = 0; k < 8; k++) {
        float4 t4 = ar[k];
        a[4*k] = t4.x; a[4*k+1] = t4.y; a[4*k+2] = t4.z; a[4*k+3] = t4.w;
    }
    GEMM32_BODY(32, g_h + e * 32)
}

__global__ void k_edge2(const float* __restrict__ w, const float* __restrict__ b, long E) {
    __shared__ float wsm[1024], bsm[32], sc[32], sh[32];
    int tid = threadIdx.x;
    for (int t = tid; t < 1024; t += 256) wsm[t] = w[t];
    if (tid < 32) { bsm[tid] = b[tid]; sc[tid] = g_bnp[tid]; sh[tid] = g_bnp[32 + tid]; }
    __syncthreads();
    long e = blockIdx.x * 256L + tid;
    if (e >= E) return;
    float a[32];
    const float4* ar = (const float4*)(g_h + e * 32);
#pragma unroll
    for (int k = 0; k < 8; k++) {
        float4 t4 = ar[k];
        a[4*k+0] = fmaxf(t4.x * sc[4*k+0] + sh[4*k+0], 0.0f);
        a[4*k+1] = fmaxf(t4.y * sc[4*k+1] + sh[4*k+1], 0.0f);
        a[4*k+2] = fmaxf(t4.z * sc[4*k+2] + sh[4*k+2], 0.0f);
        a[4*k+3] = fmaxf(t4.w * sc[4*k+3] + sh[4*k+3], 0.0f);
    }
    GEMM32_BODY(32, g_h + e * 32)
}

// per-channel sum/sumsq with block-level smem reduction (few global atomics)
__global__ void k_stat(int which, long n4, int stage) {
    const float4* d = (which == 0) ? (const float4*)g_h
                    : (which == 1) ? (const float4*)g_n1
                                   : (const float4*)g_n2;
    __shared__ float ssum[64];
    float* out = &g_sums[stage * 64];
    long tid = blockIdx.x * 256L + threadIdx.x;
    long stride = (long)gridDim.x * 256L;
    float4 s = make_float4(0,0,0,0), q = make_float4(0,0,0,0);
    for (long i = tid; i < n4; i += stride) {
        float4 v = d[i];
        s.x += v.x; s.y += v.y; s.z += v.z; s.w += v.w;
        q.x += v.x*v.x; q.y += v.y*v.y; q.z += v.z*v.z; q.w += v.w*v.w;
    }
#pragma unroll
    for (int off = 8; off < 32; off <<= 1) {
        s.x += __shfl_xor_sync(0xffffffffu, s.x, off);
        s.y += __shfl_xor_sync(0xffffffffu, s.y, off);
        s.z += __shfl_xor_sync(0xffffffffu, s.z, off);
        s.w += __shfl_xor_sync(0xffffffffu, s.w, off);
        q.x += __shfl_xor_sync(0xffffffffu, q.x, off);
        q.y += __shfl_xor_sync(0xffffffffu, q.y, off);
        q.z += __shfl_xor_sync(0xffffffffu, q.z, off);
        q.w += __shfl_xor_sync(0xffffffffu, q.w, off);
    }
    if (threadIdx.x < 64) ssum[threadIdx.x] = 0.0f;
    __syncthreads();
    int lane = threadIdx.x & 31;
    if (lane < 8) {
        int cb = lane * 4;
        atomicAdd(&ssum[cb+0], s.x); atomicAdd(&ssum[cb+1], s.y);
        atomicAdd(&ssum[cb+2], s.z); atomicAdd(&ssum[cb+3], s.w);
        atomicAdd(&ssum[32+cb+0], q.x); atomicAdd(&ssum[32+cb+1], q.y);
        atomicAdd(&ssum[32+cb+2], q.z); atomicAdd(&ssum[32+cb+3], q.w);
    }
    __syncthreads();
    if (threadIdx.x < 64) atomicAdd(&out[threadIdx.x], ssum[threadIdx.x]);
}

__global__ void k_fin(int stage, const float* __restrict__ g, const float* __restrict__ be, float n) {
    int j = threadIdx.x;
    float s  = g_sums[stage * 64 + j];
    float sq = g_sums[stage * 64 + 32 + j];
    float m = s / n;
    float var = sq / n - m * m;
    float scale = g[j] * rsqrtf(var + BN_EPS);
    g_bnp[stage * 64 + j] = scale;
    g_bnp[stage * 64 + 32 + j] = be[j] - m * scale;
}

// edge einsum + scatter: one warp/edge, fp16 T2 gather (1 KB/edge)
__global__ void k_edge3(long E) {
    __shared__ float sc[32], sh[32];
    __shared__ float smsg[8][16];
    int tid = threadIdx.x;
    if (tid < 32) { sc[tid] = g_bnp[64 + tid]; sh[tid] = g_bnp[96 + tid]; }
    __syncthreads();
    long e = (blockIdx.x * 256L + tid) >> 5;
    if (e >= E) return;
    int lane = tid & 31, wid = tid >> 5;
    int o = lane >> 1, p = lane & 1;
    int s = g_src[e];
    int d = g_dst[e];
    const float4* hrow = (const float4*)(g_h + e * 32 + p * 16);
    const uint4* trow = (const uint4*)((const char*)g_T2h + ((size_t)s * 512 + lane * 16) * 2);
    uint4 t0 = trow[0];
    uint4 t1 = trow[1];
    float tf[16];
    {
        const __half2* hp = (const __half2*)&t0;
#pragma unroll
        for (int q = 0; q < 4; q++) { float2 f = __half22float2(hp[q]); tf[2*q] = f.x; tf[2*q+1] = f.y; }
        hp = (const __half2*)&t1;
#pragma unroll
        for (int q = 0; q < 4; q++) { float2 f = __half22float2(hp[q]); tf[8+2*q] = f.x; tf[8+2*q+1] = f.y; }
    }
    float acc = 0.0f;
#pragma unroll
    for (int k = 0; k < 4; k++) {
        float4 z = hrow[k];
        int hb = p * 16 + k * 4;
        z.x = fmaxf(z.x * sc[hb+0] + sh[hb+0], 0.0f);
        z.y = fmaxf(z.y * sc[hb+1] + sh[hb+1], 0.0f);
        z.z = fmaxf(z.z * sc[hb+2] + sh[hb+2], 0.0f);
        z.w = fmaxf(z.w * sc[hb+3] + sh[hb+3], 0.0f);
        acc += z.x*tf[k*4+0] + z.y*tf[k*4+1] + z.z*tf[k*4+2] + z.w*tf[k*4+3];
    }
    acc += __shfl_xor_sync(0xffffffffu, acc, 1);
    if (p == 0) smsg[wid][o] = acc + g_B[(size_t)s * 16 + o];
    __syncwarp();
    if (lane < 4) {
        float4 m = *(float4*)&smsg[wid][lane * 4];
        red_add_v4(&g_agg[(size_t)d * 16 + lane * 4], m);
    }
}

__global__ void k_own1(const float* __restrict__ x, const float* __restrict__ w,
                       const float* __restrict__ b, int N) {
    __shared__ float wsm[1536], bsm[32];
    int tid = threadIdx.x;
    for (int t = tid; t < 1536; t += 256) wsm[t] = w[t];
    if (tid < 32) bsm[tid] = b[tid];
    __syncthreads();
    int v = blockIdx.x * 256 + tid;
    if (v >= N) return;
    float a[48];
    const float4* xr = (const float4*)(x + (size_t)v * 32);
#pragma unroll
    for (int k = 0; k < 8; k++) {
        float4 t4 = xr[k];
        a[4*k] = t4.x; a[4*k+1] = t4.y; a[4*k+2] = t4.z; a[4*k+3] = t4.w;
    }
    const float4* gr = (const float4*)(g_agg + (size_t)v * 16);
#pragma unroll
    for (int k = 0; k < 4; k++) {
        float4 t4 = gr[k];
        a[32+4*k] = t4.x; a[32+4*k+1] = t4.y; a[32+4*k+2] = t4.z; a[32+4*k+3] = t4.w;
    }
    GEMM32_BODY(48, g_n1 + (size_t)v * 32)
}

__global__ void k_own2(const float* __restrict__ w, const float* __restrict__ b, int N) {
    __shared__ float wsm[1024], bsm[32], sc[32], sh[32];
    int tid = threadIdx.x;
    for (int t = tid; t < 1024; t += 256) wsm[t] = w[t];
    if (tid < 32) { bsm[tid] = b[tid]; sc[tid] = g_bnp[128 + tid]; sh[tid] = g_bnp[160 + tid]; }
    __syncthreads();
    int v = blockIdx.x * 256 + tid;
    if (v >= N) return;
    float a[32];
    const float4* ar = (const float4*)(g_n1 + (size_t)v * 32);
#pragma unroll
    for (int k = 0; k < 8; k++) {
        float4 t4 = ar[k];
        a[4*k+0] = fmaxf(t4.x * sc[4*k+0] + sh[4*k+0], 0.0f);
        a[4*k+1] = fmaxf(t4.y * sc[4*k+1] + sh[4*k+1], 0.0f);
        a[4*k+2] = fmaxf(t4.z * sc[4*k+2] + sh[4*k+2], 0.0f);
        a[4*k+3] = fmaxf(t4.w * sc[4*k+3] + sh[4*k+3], 0.0f);
    }
    GEMM32_BODY(32, g_n2 + (size_t)v * 32)
}

__global__ void k_own3(const float* __restrict__ w, const float* __restrict__ b,
                       float* __restrict__ out, int N) {
    __shared__ float wsm[1024], bsm[32], sc[32], sh[32];
    int tid = threadIdx.x;
    for (int t = tid; t < 1024; t += 256) wsm[t] = w[t];
    if (tid < 32) { bsm[tid] = b[tid]; sc[tid] = g_bnp[192 + tid]; sh[tid] = g_bnp[224 + tid]; }
    __syncthreads();
    int v = blockIdx.x * 256 + tid;
    if (v >= N) return;
    float a[32];
    const float4* ar = (const float4*)(g_n2 + (size_t)v * 32);
#pragma unroll
    for (int k = 0; k < 8; k++) {
        float4 t4 = ar[k];
        a[4*k+0] = fmaxf(t4.x * sc[4*k+0] + sh[4*k+0], 0.0f);
        a[4*k+1] = fmaxf(t4.y * sc[4*k+1] + sh[4*k+1], 0.0f);
        a[4*k+2] = fmaxf(t4.z * sc[4*k+2] + sh[4*k+2], 0.0f);
        a[4*k+3] = fmaxf(t4.w * sc[4*k+3] + sh[4*k+3], 0.0f);
    }
    GEMM32_BODY(32, out + (size_t)v * 32)
}

extern "C" void kernel_launch(void* const* d_in, const int* in_sizes, int n_in,
                              void* d_out, int out_size) {
    const float* x    = (const float*)d_in[0];
    const float* ea   = (const float*)d_in[1];
    const void*  ei   = d_in[2];
    const float* mw1  = (const float*)d_in[3];
    const float* mb1  = (const float*)d_in[4];
    const float* mg1  = (const float*)d_in[5];
    const float* mbe1 = (const float*)d_in[6];
    const float* mw2  = (const float*)d_in[7];
    const float* mb2  = (const float*)d_in[8];
    const float* mg2  = (const float*)d_in[9];
    const float* mbe2 = (const float*)d_in[10];
    const float* mw3  = (const float*)d_in[11];
    const float* mb3  = (const float*)d_in[12];
    const float* rw   = (const float*)d_in[13];
    const float* rb   = (const float*)d_in[14];
    const float* ow1  = (const float*)d_in[15];
    const float* ob1  = (const float*)d_in[16];
    const float* og1  = (const float*)d_in[17];
    const float* obe1 = (const float*)d_in[18];
    const float* ow2  = (const float*)d_in[19];
    const float* ob2  = (const float*)d_in[20];
    const float* og2  = (const float*)d_in[21];
    const float* obe2 = (const float*)d_in[22];
    const float* ow3  = (const float*)d_in[23];
    const float* ob3  = (const float*)d_in[24];
    float* out = (float*)d_out;

    int  N = in_sizes[0] / SD;
    long E = (long)in_sizes[1] / SD;

    cudaFuncSetAttribute(k_T, cudaFuncAttributeMaxDynamicSharedMemorySize, 69632);

    int nb256  = (N + 255) / 256;
    long eb256 = (E + 255) / 256;
    long eb3   = (E * 32 + 255) / 256;

    k_detect<<<1, 256>>>(ei, E, N);
    k_convert<<<(unsigned)eb256, 256>>>(ei, E);
    k_w3rz<<<64, 256>>>(mw3);
    k_edge1<<<(unsigned)eb256, 256>>>(ea, mw1, mb1, E);
    k_T<<<(N + 31) / 32, 256, 69632>>>(x, N);
    k_rootB<<<nb256, 256>>>(x, rw, rb, mb3, N);
    k_stat<<<296, 256>>>(0, E * 8, 0);
    k_fin<<<1, 32>>>(0, mg1, mbe1, (float)E);
    k_edge2<<<(unsigned)eb256, 256>>>(mw2, mb2, E);
    k_stat<<<296, 256>>>(0, E * 8, 1);
    k_fin<<<1, 32>>>(1, mg2, mbe2, (float)E);
    k_edge3<<<(unsigned)eb3, 256>>>(E);
    k_own1<<<nb256, 256>>>(x, ow1, ob1, N);
    k_stat<<<148, 256>>>(1, (long)N * 8, 2);
    k_fin<<<1, 32>>>(2, og1, obe1, (float)N);
    k_own2<<<nb256, 256>>>(ow2, ob2, N);
    k_stat<<<148, 256>>>(2, (long)N * 8, 3);
    k_fin<<<1, 32>>>(3, og2, obe2, (float)N);
    k_own3<<<nb256, 256>>>(ow3, ob3, out, N);
}